// round 1
// baseline (speedup 1.0000x reference)
#include <cuda_runtime.h>
#include <math.h>

#define N_NODES 100000
#define N_RELS  500
#define DIMV    200
#define N_EDG   200000

// ---------------- scratch (device globals; no allocation allowed) ----------
__device__ float g_h  [(size_t)N_NODES * DIMV];
__device__ float g_r  [(size_t)N_RELS  * DIMV];
__device__ float g_A  [(size_t)N_NODES * DIMV];
__device__ float g_rA [(size_t)N_RELS  * DIMV];
__device__ float g_agg[(size_t)N_NODES * DIMV];
__device__ float g_c1 [(size_t)N_NODES * DIMV];
__device__ float g_c2 [(size_t)N_NODES * DIMV];
__device__ float g_gt [(size_t)N_NODES * DIMV];
__device__ float g_deg[N_NODES];

// ---------------- small utility kernels ------------------------------------
__global__ void zero4_kernel(float4* __restrict__ p, int n4) {
    int i = blockIdx.x * blockDim.x + threadIdx.x;
    if (i < n4) p[i] = make_float4(0.f, 0.f, 0.f, 0.f);
}

// warp-per-row l2 normalize
__global__ void l2norm_kernel(const float* __restrict__ in, float* __restrict__ out, int rows) {
    int warp = (blockIdx.x * blockDim.x + threadIdx.x) >> 5;
    int lane = threadIdx.x & 31;
    if (warp >= rows) return;
    const float* p = in + (size_t)warp * DIMV;
    float s = 0.f;
    for (int j = lane; j < DIMV; j += 32) { float v = p[j]; s += v * v; }
    #pragma unroll
    for (int o = 16; o; o >>= 1) s += __shfl_xor_sync(0xffffffffu, s, o);
    float inv = 1.f / fmaxf(sqrtf(s), 1e-12f);
    float* q = out + (size_t)warp * DIMV;
    for (int j = lane; j < DIMV; j += 32) q[j] = p[j] * inv;
}

__global__ void deg_kernel(const int* __restrict__ e, float* __restrict__ deg) {
    int i = blockIdx.x * blockDim.x + threadIdx.x;
    if (i < N_EDG) atomicAdd(&deg[e[3 * i + 2]], 1.0f);
}

// warp-per-edge: agg[dst] += A[src] + rA[rel], via vectorized no-return reduction
__global__ void scatter_kernel(const int* __restrict__ e,
                               const float* __restrict__ A,
                               const float* __restrict__ rA,
                               float* __restrict__ agg) {
    int warp = (blockIdx.x * blockDim.x + threadIdx.x) >> 5;
    int lane = threadIdx.x & 31;
    if (warp >= N_EDG) return;
    int src = e[3 * warp + 0];
    int rel = e[3 * warp + 1];
    int dst = e[3 * warp + 2];
    const float4* a  = (const float4*)(A  + (size_t)src * DIMV);
    const float4* ra = (const float4*)(rA + (size_t)rel * DIMV);
    float4*       d  = (float4*)(agg + (size_t)dst * DIMV);
    #pragma unroll 2
    for (int c = lane; c < DIMV / 4; c += 32) {
        float4 va = a[c], vr = ra[c];
        float4 v = make_float4(va.x + vr.x, va.y + vr.y, va.z + vr.z, va.w + vr.w);
        asm volatile("red.global.add.v4.f32 [%0], {%1,%2,%3,%4};"
                     :: "l"(d + c), "f"(v.x), "f"(v.y), "f"(v.z), "f"(v.w)
                     : "memory");
    }
}

// ---------------- SGEMM: C[M,200] = A[M,200] @ B[200,200] (+ epilogue) ------
// MODE 0: plain
// MODE 1: C = acc + agg[row]/max(deg[row],1)
// MODE 2: C = sigmoid(acc + bias[col])
#define BM 128
#define BN 128
#define BK 8

template <int MODE>
__global__ void __launch_bounds__(256, 2)
gemm_kernel(const float* __restrict__ A, const float* __restrict__ B,
            float* __restrict__ C, int M,
            const float* __restrict__ agg, const float* __restrict__ deg,
            const float* __restrict__ bias) {
    __shared__ __align__(16) float As[BK][BM];
    __shared__ __align__(16) float Bs[BK][BN];

    int tid  = threadIdx.x;
    int row0 = blockIdx.x * BM;
    int n0   = blockIdx.y * BN;
    int tr   = tid / 16;
    int tc   = tid % 16;

    int aRow = tid >> 1;           // 0..127
    int aK   = (tid & 1) * 4;      // 0 or 4
    int bK   = tid >> 5;           // 0..7
    int bCol = (tid & 31) * 4;     // 0..124

    float acc[8][8];
    #pragma unroll
    for (int i = 0; i < 8; i++)
        #pragma unroll
        for (int j = 0; j < 8; j++) acc[i][j] = 0.f;

    for (int k0 = 0; k0 < DIMV; k0 += BK) {
        float4 av = make_float4(0.f, 0.f, 0.f, 0.f);
        int gr = row0 + aRow;
        if (gr < M) av = *(const float4*)(A + (size_t)gr * DIMV + k0 + aK);
        As[aK + 0][aRow] = av.x;
        As[aK + 1][aRow] = av.y;
        As[aK + 2][aRow] = av.z;
        As[aK + 3][aRow] = av.w;

        float4 bv = make_float4(0.f, 0.f, 0.f, 0.f);
        int gc = n0 + bCol;
        if (gc < DIMV) bv = *(const float4*)(B + (size_t)(k0 + bK) * DIMV + gc);
        *(float4*)&Bs[bK][bCol] = bv;

        __syncthreads();
        #pragma unroll
        for (int k = 0; k < BK; k++) {
            float a[8], b[8];
            *(float4*)&a[0] = *(float4*)&As[k][tr * 4];
            *(float4*)&a[4] = *(float4*)&As[k][64 + tr * 4];
            *(float4*)&b[0] = *(float4*)&Bs[k][tc * 4];
            *(float4*)&b[4] = *(float4*)&Bs[k][64 + tc * 4];
            #pragma unroll
            for (int i = 0; i < 8; i++)
                #pragma unroll
                for (int j = 0; j < 8; j++)
                    acc[i][j] += a[i] * b[j];
        }
        __syncthreads();
    }

    #pragma unroll
    for (int i = 0; i < 8; i++) {
        int r = row0 + ((i < 4) ? (tr * 4 + i) : (64 + tr * 4 + i - 4));
        if (r >= M) continue;
        float invdeg = 1.0f;
        if (MODE == 1) invdeg = 1.0f / fmaxf(deg[r], 1.0f);
        #pragma unroll
        for (int jj = 0; jj < 2; jj++) {
            int c = n0 + ((jj == 0) ? (tc * 4) : (64 + tc * 4));
            if (c >= DIMV) continue;
            float4 v = make_float4(acc[i][jj * 4 + 0], acc[i][jj * 4 + 1],
                                   acc[i][jj * 4 + 2], acc[i][jj * 4 + 3]);
            if (MODE == 1) {
                float4 ag = *(const float4*)(agg + (size_t)r * DIMV + c);
                v.x += ag.x * invdeg; v.y += ag.y * invdeg;
                v.z += ag.z * invdeg; v.w += ag.w * invdeg;
            } else if (MODE == 2) {
                float4 bb = *(const float4*)(bias + c);
                v.x = 1.f / (1.f + expf(-(v.x + bb.x)));
                v.y = 1.f / (1.f + expf(-(v.y + bb.y)));
                v.z = 1.f / (1.f + expf(-(v.z + bb.z)));
                v.w = 1.f / (1.f + expf(-(v.w + bb.w)));
            }
            *(float4*)(C + (size_t)r * DIMV + c) = v;
        }
    }
}

// ---------------- fused final: h = l2norm(g*l2norm(c2) + (1-g)*h) ----------
__global__ void final_kernel(const float* __restrict__ cur2,
                             const float* __restrict__ gate,
                             const float* __restrict__ hin,
                             float* __restrict__ hout) {
    int warp = (blockIdx.x * blockDim.x + threadIdx.x) >> 5;
    int lane = threadIdx.x & 31;
    if (warp >= N_NODES) return;
    size_t base = (size_t)warp * DIMV;

    float cv[7], gv[7], hv[7];
    int cnt = 0;
    float s = 0.f;
    for (int j = lane; j < DIMV; j += 32) {
        float x = cur2[base + j];
        cv[cnt] = x;
        gv[cnt] = gate[base + j];
        hv[cnt] = hin[base + j];
        s += x * x;
        cnt++;
    }
    #pragma unroll
    for (int o = 16; o; o >>= 1) s += __shfl_xor_sync(0xffffffffu, s, o);
    float inv = 1.f / fmaxf(sqrtf(s), 1e-12f);

    float s2 = 0.f;
    for (int i = 0; i < cnt; i++) {
        float v = gv[i] * (cv[i] * inv) + (1.f - gv[i]) * hv[i];
        cv[i] = v;
        s2 += v * v;
    }
    #pragma unroll
    for (int o = 16; o; o >>= 1) s2 += __shfl_xor_sync(0xffffffffu, s2, o);
    float inv2 = 1.f / fmaxf(sqrtf(s2), 1e-12f);

    cnt = 0;
    for (int j = lane; j < DIMV; j += 32) {
        hout[base + j] = cv[cnt] * inv2;
        cnt++;
    }
}

// ---------------- host launcher --------------------------------------------
extern "C" void kernel_launch(void* const* d_in, const int* in_sizes, int n_in,
                              void* d_out, int out_size) {
    const int*   edges = (const int*)d_in[0];
    const float* ent   = (const float*)d_in[1];
    const float* rele  = (const float*)d_in[2];
    const float* Wm1   = (const float*)d_in[3];
    const float* Wl1   = (const float*)d_in[4];
    const float* Wm2   = (const float*)d_in[5];
    const float* Wl2   = (const float*)d_in[6];
    const float* Wg    = (const float*)d_in[7];
    const float* bg    = (const float*)d_in[8];
    float* out = (float*)d_out;

    float *h, *r, *A, *rA, *agg, *c1, *c2, *gt, *deg;
    cudaGetSymbolAddress((void**)&h,   g_h);
    cudaGetSymbolAddress((void**)&r,   g_r);
    cudaGetSymbolAddress((void**)&A,   g_A);
    cudaGetSymbolAddress((void**)&rA,  g_rA);
    cudaGetSymbolAddress((void**)&agg, g_agg);
    cudaGetSymbolAddress((void**)&c1,  g_c1);
    cudaGetSymbolAddress((void**)&c2,  g_c2);
    cudaGetSymbolAddress((void**)&gt,  g_gt);
    cudaGetSymbolAddress((void**)&deg, g_deg);

    const dim3 gemm_grid((N_NODES + BM - 1) / BM, 2);
    const dim3 gemm_grid_r((N_RELS + BM - 1) / BM, 2);
    const int  n_agg4 = (N_NODES * DIMV) / 4;
    const int  n_deg4 = N_NODES / 4;

    l2norm_kernel<<<(N_NODES + 7) / 8, 256>>>(ent, h, N_NODES);
    l2norm_kernel<<<(N_RELS + 7) / 8, 256>>>(rele, r, N_RELS);

    for (int t = 0; t < 3; t++) {
        const int* e = edges + (size_t)t * N_EDG * 3;

        zero4_kernel<<<(n_deg4 + 255) / 256, 256>>>((float4*)deg, n_deg4);
        deg_kernel<<<(N_EDG + 255) / 256, 256>>>(e, deg);

        // ---- layer 1 ----
        gemm_kernel<0><<<gemm_grid,   256>>>(h, Wm1, A,  N_NODES, nullptr, nullptr, nullptr);
        gemm_kernel<0><<<gemm_grid_r, 256>>>(r, Wm1, rA, N_RELS,  nullptr, nullptr, nullptr);
        zero4_kernel<<<(n_agg4 + 255) / 256, 256>>>((float4*)agg, n_agg4);
        scatter_kernel<<<(N_EDG + 7) / 8, 256>>>(e, A, rA, agg);
        gemm_kernel<1><<<gemm_grid,   256>>>(h, Wl1, c1, N_NODES, agg, deg, nullptr);

        // ---- layer 2 ----
        gemm_kernel<0><<<gemm_grid,   256>>>(c1, Wm2, A,  N_NODES, nullptr, nullptr, nullptr);
        gemm_kernel<0><<<gemm_grid_r, 256>>>(r,  Wm2, rA, N_RELS,  nullptr, nullptr, nullptr);
        zero4_kernel<<<(n_agg4 + 255) / 256, 256>>>((float4*)agg, n_agg4);
        scatter_kernel<<<(N_EDG + 7) / 8, 256>>>(e, A, rA, agg);
        gemm_kernel<1><<<gemm_grid,   256>>>(c1, Wl2, c2, N_NODES, agg, deg, nullptr);

        // ---- gate + update ----
        gemm_kernel<2><<<gemm_grid, 256>>>(h, Wg, gt, N_NODES, nullptr, nullptr, bg);
        final_kernel<<<(N_NODES + 7) / 8, 256>>>(c2, gt, h, (t == 2) ? out : h);
    }
}

// round 4
// speedup vs baseline: 2.0537x; 2.0537x over previous
#include <cuda_runtime.h>
#include <math.h>
#include <stdint.h>

#define N_NODES 100000
#define N_RELS  500
#define DIMV    200
#define N_EDG   200000
#define NP1     640   // packed [Wm1|Wl1|Wg] + pad
#define NP2     448   // packed [Wm2|Wl2] + pad
#define BM      128
#define SA      204   // A smem row stride (conflict-free for frag loads)
#define SB      72    // B smem row stride (conflict-free)
#define SMEMB   ((BM*SA + DIMV*SB) * 4)

// ---------------- scratch (device globals; no allocation allowed) ----------
__device__ float g_h  [(size_t)N_NODES * DIMV];
__device__ float g_r  [(size_t)N_RELS  * DIMV];
__device__ float g_P1 [(size_t)N_NODES * NP1];   // [A1 | L1 | Graw | pad]
__device__ float g_P2 [(size_t)N_NODES * NP2];   // [A2 | L2 | pad]
__device__ float g_agg1[(size_t)N_NODES * DIMV];
__device__ float g_agg2[(size_t)N_NODES * DIMV];
__device__ float g_rA1[(size_t)N_RELS * DIMV];
__device__ float g_rA2[(size_t)N_RELS * DIMV];
__device__ float g_W1 [200 * NP1];
__device__ float g_W2 [200 * NP2];
__device__ float g_deg[N_NODES];

// ---------------- helpers ---------------------------------------------------
__device__ __forceinline__ float to_tf32(float x) {
    float y;
    asm("cvt.rna.tf32.f32 %0, %1;" : "=f"(y) : "f"(x));
    return y;
}

__device__ __forceinline__ void mma8(float* c, const uint32_t* a, const uint32_t* b) {
    asm volatile(
        "mma.sync.aligned.m16n8k8.row.col.f32.tf32.tf32.f32 "
        "{%0,%1,%2,%3},{%4,%5,%6,%7},{%8,%9},{%0,%1,%2,%3};"
        : "+f"(c[0]), "+f"(c[1]), "+f"(c[2]), "+f"(c[3])
        : "r"(a[0]), "r"(a[1]), "r"(a[2]), "r"(a[3]), "r"(b[0]), "r"(b[1]));
}

// ---------------- small utility kernels ------------------------------------
__global__ void zero4_kernel(float4* __restrict__ p, int n4) {
    int i = blockIdx.x * blockDim.x + threadIdx.x;
    if (i < n4) p[i] = make_float4(0.f, 0.f, 0.f, 0.f);
}

__global__ void l2norm_kernel(const float* __restrict__ in, float* __restrict__ out, int rows) {
    int warp = (blockIdx.x * blockDim.x + threadIdx.x) >> 5;
    int lane = threadIdx.x & 31;
    if (warp >= rows) return;
    const float* p = in + (size_t)warp * DIMV;
    float s = 0.f;
    for (int j = lane; j < DIMV; j += 32) { float v = p[j]; s += v * v; }
    #pragma unroll
    for (int o = 16; o; o >>= 1) s += __shfl_xor_sync(0xffffffffu, s, o);
    float inv = 1.f / fmaxf(sqrtf(s), 1e-12f);
    float* q = out + (size_t)warp * DIMV;
    for (int j = lane; j < DIMV; j += 32) q[j] = p[j] * inv;
}

__global__ void deg_kernel(const int* __restrict__ e, float* __restrict__ deg) {
    int i = blockIdx.x * blockDim.x + threadIdx.x;
    if (i < N_EDG) atomicAdd(&deg[e[3 * i + 2]], 1.0f);
}

__global__ void pack3_kernel(const float* __restrict__ Wa, const float* __restrict__ Wb,
                             const float* __restrict__ Wc, float* __restrict__ out) {
    int idx = blockIdx.x * blockDim.x + threadIdx.x;
    if (idx >= 200 * NP1) return;
    int r = idx / NP1, c = idx % NP1;
    float v = 0.f;
    if (c < 200)      v = Wa[r * 200 + c];
    else if (c < 400) v = Wb[r * 200 + c - 200];
    else if (c < 600) v = Wc[r * 200 + c - 400];
    out[idx] = v;
}

__global__ void pack2_kernel(const float* __restrict__ Wa, const float* __restrict__ Wb,
                             float* __restrict__ out) {
    int idx = blockIdx.x * blockDim.x + threadIdx.x;
    if (idx >= 200 * NP2) return;
    int r = idx / NP2, c = idx % NP2;
    float v = 0.f;
    if (c < 200)      v = Wa[r * 200 + c];
    else if (c < 400) v = Wb[r * 200 + c - 200];
    out[idx] = v;
}

// warp-per-edge scatter with strided A; red.global (no return) vectorized
__global__ void scatter_kernel(const int* __restrict__ e,
                               const float* __restrict__ A, int astr,
                               const float* __restrict__ rA,
                               float* __restrict__ agg) {
    int warp = (blockIdx.x * blockDim.x + threadIdx.x) >> 5;
    int lane = threadIdx.x & 31;
    if (warp >= N_EDG) return;
    int src = e[3 * warp + 0];
    int rel = e[3 * warp + 1];
    int dst = e[3 * warp + 2];
    const float4* a  = (const float4*)(A  + (size_t)src * astr);
    const float4* ra = (const float4*)(rA + (size_t)rel * DIMV);
    float4*       d  = (float4*)(agg + (size_t)dst * DIMV);
    #pragma unroll 2
    for (int c = lane; c < DIMV / 4; c += 32) {
        float4 va = a[c], vr = ra[c];
        float4 v = make_float4(va.x + vr.x, va.y + vr.y, va.z + vr.z, va.w + vr.w);
        asm volatile("red.global.add.v4.f32 [%0], {%1,%2,%3,%4};"
                     :: "l"(d + c), "f"(v.x), "f"(v.y), "f"(v.z), "f"(v.w)
                     : "memory");
    }
}

// ---------------- tf32 MMA GEMM: Out[M, NT*64] = A[M,200] @ Bp[200, npack] --
// AFILL 0: A row = Asrc[row * asrcStride + k]
// AFILL 1: A row = Asrc[row * asrcStride + k] + agg[row*200+k] / max(deg[row],1)
// Block: 128 rows, A slab resident in SMEM (tf32), sweeps NT 64-col tiles.
template <int AFILL>
__global__ void __launch_bounds__(256)
mma_gemm(const float* __restrict__ Asrc, int asrcStride,
         const float* __restrict__ agg, const float* __restrict__ deg,
         const float* __restrict__ Bp, int npack,
         float* __restrict__ Out, int ostride, int realN,
         int M, int NT) {
    extern __shared__ float smf[];
    float* As = smf;             // [128][SA]
    float* Bs = smf + BM * SA;   // [200][SB]
    const int tid  = threadIdx.x;
    const int row0 = blockIdx.x * BM;

    // ---- A fill (once) ----
    {
        int r = tid >> 1;
        int cbase = (tid & 1) * 100;
        int grow = row0 + r;
        bool valid = grow < M;
        float invd = 1.f;
        if (AFILL == 1 && valid) invd = 1.f / fmaxf(deg[grow], 1.f);
        const float* ap = Asrc + (size_t)grow * asrcStride;
        const float* gp = agg + (size_t)grow * DIMV;
        #pragma unroll
        for (int i = 0; i < 25; i++) {
            int c = cbase + i * 4;
            float4 v = make_float4(0.f, 0.f, 0.f, 0.f);
            if (valid) {
                v = *(const float4*)(ap + c);
                if (AFILL == 1) {
                    float4 g4 = *(const float4*)(gp + c);
                    v.x += g4.x * invd; v.y += g4.y * invd;
                    v.z += g4.z * invd; v.w += g4.w * invd;
                }
            }
            float* d = As + r * SA + c;
            d[0] = to_tf32(v.x); d[1] = to_tf32(v.y);
            d[2] = to_tf32(v.z); d[3] = to_tf32(v.w);
        }
    }
    __syncthreads();

    const int wid = tid >> 5, lane = tid & 31;
    const int gid = lane >> 2, tig = lane & 3;
    const int wm = (wid >> 1) * 32;   // warp m offset (4 warps)
    const int wn = (wid & 1) * 32;    // warp n offset (2 warps)
    const uint32_t* Asu = (const uint32_t*)As;
    const uint32_t* Bsu = (const uint32_t*)Bs;

    for (int nt = 0; nt < NT; nt++) {
        int n0 = nt * 64;
        // ---- B fill: 200 x 64 tile, tf32 ----
        for (int idx = tid; idx < 200 * 16; idx += 256) {
            int r = idx >> 4, c = (idx & 15) << 2;
            float4 v = *(const float4*)(Bp + (size_t)r * npack + n0 + c);
            float* d = Bs + r * SB + c;
            d[0] = to_tf32(v.x); d[1] = to_tf32(v.y);
            d[2] = to_tf32(v.z); d[3] = to_tf32(v.w);
        }
        __syncthreads();

        float acc[2][4][4];
        #pragma unroll
        for (int mi = 0; mi < 2; mi++)
            #pragma unroll
            for (int ni = 0; ni < 4; ni++)
                #pragma unroll
                for (int q = 0; q < 4; q++) acc[mi][ni][q] = 0.f;

        #pragma unroll
        for (int ks = 0; ks < 25; ks++) {
            int k0 = ks * 8;
            uint32_t a[2][4];
            #pragma unroll
            for (int mi = 0; mi < 2; mi++) {
                int r0a = (wm + mi * 16 + gid) * SA + k0;
                int r1a = r0a + 8 * SA;
                a[mi][0] = Asu[r0a + tig];
                a[mi][1] = Asu[r1a + tig];
                a[mi][2] = Asu[r0a + 4 + tig];
                a[mi][3] = Asu[r1a + 4 + tig];
            }
            uint32_t b[4][2];
            #pragma unroll
            for (int ni = 0; ni < 4; ni++) {
                int cb = wn + ni * 8 + gid;
                b[ni][0] = Bsu[(k0 + tig) * SB + cb];
                b[ni][1] = Bsu[(k0 + tig + 4) * SB + cb];
            }
            #pragma unroll
            for (int mi = 0; mi < 2; mi++)
                #pragma unroll
                for (int ni = 0; ni < 4; ni++)
                    mma8(acc[mi][ni], a[mi], b[ni]);
        }

        // ---- epilogue: masked strided stores ----
        #pragma unroll
        for (int mi = 0; mi < 2; mi++) {
            #pragma unroll
            for (int ni = 0; ni < 4; ni++) {
                int grow = row0 + wm + mi * 16 + gid;
                int gcol = n0 + wn + ni * 8 + tig * 2;
                if (gcol < realN) {
                    if (grow < M)
                        *(float2*)(Out + (size_t)grow * ostride + gcol) =
                            make_float2(acc[mi][ni][0], acc[mi][ni][1]);
                    if (grow + 8 < M)
                        *(float2*)(Out + (size_t)(grow + 8) * ostride + gcol) =
                            make_float2(acc[mi][ni][2], acc[mi][ni][3]);
                }
            }
        }
        __syncthreads();
    }
}

// ------- fused final: gate=sig(Graw+b); c2=L2raw+agg2/deg; h'=l2n(g*l2n(c2)+(1-g)h)
__global__ void final_kernel(const float* __restrict__ P1,   // Graw at col 400, stride NP1
                             const float* __restrict__ bias,
                             const float* __restrict__ P2,   // L2raw at col 200, stride NP2
                             const float* __restrict__ agg2,
                             const float* __restrict__ deg,
                             const float* __restrict__ hin,
                             float* __restrict__ hout) {
    int warp = (blockIdx.x * blockDim.x + threadIdx.x) >> 5;
    int lane = threadIdx.x & 31;
    if (warp >= N_NODES) return;
    const float* graw = P1 + (size_t)warp * NP1 + 400;
    const float* l2r  = P2 + (size_t)warp * NP2 + 200;
    const float* ag   = agg2 + (size_t)warp * DIMV;
    const float* hp   = hin + (size_t)warp * DIMV;
    float invd = 1.f / fmaxf(deg[warp], 1.f);

    float cv[7], gv[7], hv[7];
    int cnt = 0;
    float s = 0.f;
    for (int j = lane; j < DIMV; j += 32) {
        float x = l2r[j] + ag[j] * invd;
        cv[cnt] = x;
        gv[cnt] = 1.f / (1.f + expf(-(graw[j] + bias[j])));
        hv[cnt] = hp[j];
        s += x * x;
        cnt++;
    }
    #pragma unroll
    for (int o = 16; o; o >>= 1) s += __shfl_xor_sync(0xffffffffu, s, o);
    float inv = 1.f / fmaxf(sqrtf(s), 1e-12f);

    float s2 = 0.f;
    for (int i = 0; i < cnt; i++) {
        float v = gv[i] * (cv[i] * inv) + (1.f - gv[i]) * hv[i];
        cv[i] = v;
        s2 += v * v;
    }
    #pragma unroll
    for (int o = 16; o; o >>= 1) s2 += __shfl_xor_sync(0xffffffffu, s2, o);
    float inv2 = 1.f / fmaxf(sqrtf(s2), 1e-12f);

    float* op = hout + (size_t)warp * DIMV;
    cnt = 0;
    for (int j = lane; j < DIMV; j += 32) { op[j] = cv[cnt] * inv2; cnt++; }
}

// ---------------- host launcher --------------------------------------------
extern "C" void kernel_launch(void* const* d_in, const int* in_sizes, int n_in,
                              void* d_out, int out_size) {
    const int*   edges = (const int*)d_in[0];
    const float* ent   = (const float*)d_in[1];
    const float* rele  = (const float*)d_in[2];
    const float* Wm1   = (const float*)d_in[3];
    const float* Wl1   = (const float*)d_in[4];
    const float* Wm2   = (const float*)d_in[5];
    const float* Wl2   = (const float*)d_in[6];
    const float* Wg    = (const float*)d_in[7];
    const float* bg    = (const float*)d_in[8];
    float* out = (float*)d_out;

    float *h, *r, *P1, *P2, *agg1, *agg2, *rA1, *rA2, *W1, *W2, *deg;
    cudaGetSymbolAddress((void**)&h,    g_h);
    cudaGetSymbolAddress((void**)&r,    g_r);
    cudaGetSymbolAddress((void**)&P1,   g_P1);
    cudaGetSymbolAddress((void**)&P2,   g_P2);
    cudaGetSymbolAddress((void**)&agg1, g_agg1);
    cudaGetSymbolAddress((void**)&agg2, g_agg2);
    cudaGetSymbolAddress((void**)&rA1,  g_rA1);
    cudaGetSymbolAddress((void**)&rA2,  g_rA2);
    cudaGetSymbolAddress((void**)&W1,   g_W1);
    cudaGetSymbolAddress((void**)&W2,   g_W2);
    cudaGetSymbolAddress((void**)&deg,  g_deg);

    cudaFuncSetAttribute(mma_gemm<0>, cudaFuncAttributeMaxDynamicSharedMemorySize, SMEMB);
    cudaFuncSetAttribute(mma_gemm<1>, cudaFuncAttributeMaxDynamicSharedMemorySize, SMEMB);

    const int grid_m  = (N_NODES + BM - 1) / BM;  // 782
    const int grid_mr = (N_RELS + BM - 1) / BM;   // 4
    const int n_agg4  = (N_NODES * DIMV) / 4;
    const int n_deg4  = N_NODES / 4;

    l2norm_kernel<<<(N_NODES + 7) / 8, 256>>>(ent, h, N_NODES);
    l2norm_kernel<<<(N_RELS + 7) / 8, 256>>>(rele, r, N_RELS);
    pack3_kernel<<<(200 * NP1 + 255) / 256, 256>>>(Wm1, Wl1, Wg, W1);
    pack2_kernel<<<(200 * NP2 + 255) / 256, 256>>>(Wm2, Wl2, W2);

    // time-invariant: rA1 = r@Wm1, rA2 = r@Wm2 (first 200 packed cols)
    mma_gemm<0><<<grid_mr, 256, SMEMB>>>(r, DIMV, nullptr, nullptr, W1, NP1,
                                         rA1, DIMV, DIMV, N_RELS, 4);
    mma_gemm<0><<<grid_mr, 256, SMEMB>>>(r, DIMV, nullptr, nullptr, W2, NP2,
                                         rA2, DIMV, DIMV, N_RELS, 4);

    for (int t = 0; t < 3; t++) {
        const int* e = edges + (size_t)t * N_EDG * 3;

        zero4_kernel<<<(n_deg4 + 255) / 256, 256>>>((float4*)deg, n_deg4);
        deg_kernel<<<(N_EDG + 255) / 256, 256>>>(e, deg);
        zero4_kernel<<<(n_agg4 + 255) / 256, 256>>>((float4*)agg1, n_agg4);

        // P1 = h @ [Wm1 | Wl1 | Wg]
        mma_gemm<0><<<grid_m, 256, SMEMB>>>(h, DIMV, nullptr, nullptr, W1, NP1,
                                            P1, NP1, 600, N_NODES, 10);
        scatter_kernel<<<(N_EDG + 7) / 8, 256>>>(e, P1, NP1, rA1, agg1);

        zero4_kernel<<<(n_agg4 + 255) / 256, 256>>>((float4*)agg2, n_agg4);
        // P2 = c1 @ [Wm2 | Wl2], c1 = L1 + agg1/deg computed on the fly
        mma_gemm<1><<<grid_m, 256, SMEMB>>>(P1 + 200, NP1, agg1, deg, W2, NP2,
                                            P2, NP2, 400, N_NODES, 7);
        scatter_kernel<<<(N_EDG + 7) / 8, 256>>>(e, P2, NP2, rA2, agg2);

        final_kernel<<<(N_NODES + 7) / 8, 256>>>(P1, bg, P2, agg2, deg, h,
                                                 (t == 2) ? out : h);
    }
}